// round 1
// baseline (speedup 1.0000x reference)
#include <cuda_runtime.h>

#define D3 384
#define MTREE 2047
#define NT 32
#define NN 65504   // 32 * 2047

// Scratch (device globals: no allocation in kernel_launch)
__device__ float g_wxiou[NN * D3];   // per-node W_iou*x + b_iou
__device__ float g_wxf[NN * 128];    // per internal node W_f*x + b_f
__device__ float g_c[NN * 128];      // cell state
__device__ float g_f[NN * 128];      // forget gate keyed by CHILD node

__device__ __forceinline__ float sigf(float x) {
    return 1.0f / (1.0f + __expf(-x));
}
__device__ __forceinline__ float tanhfast(float x) {
    // 1 - 2/(e^{2x}+1): saturates correctly at +/-inf with __expf
    return 1.0f - 2.0f / (__expf(2.0f * x) + 1.0f);
}

// ---------------------------------------------------------------------------
// K1: g_wxiou = features @ W_iou + b_iou   (65504 x 128 @ 128 x 384)
// BM=32 rows per block, 256 threads, thread computes 4 rows x 4 cols x 3 sets.
// ---------------------------------------------------------------------------
__global__ __launch_bounds__(256) void k_gemm_wxiou(
    const float* __restrict__ A, const float* __restrict__ B,
    const float* __restrict__ bias)
{
    __shared__ float As[128 * 33];   // As[k*33 + r], transposed, padded
    __shared__ float Bs[16 * D3];
    const int tid = threadIdx.x;
    const int row0 = blockIdx.x * 32;

    for (int i = tid; i < 32 * 128; i += 256) {
        int r = i >> 7, k = i & 127;
        As[k * 33 + r] = A[(row0 + r) * 128 + k];
    }

    float acc[3][4][4];
#pragma unroll
    for (int s = 0; s < 3; s++)
#pragma unroll
        for (int r = 0; r < 4; r++)
#pragma unroll
            for (int c = 0; c < 4; c++) acc[s][r][c] = 0.0f;

    const int cg4 = (tid & 31) * 4;
    const int rg4 = (tid >> 5) * 4;

    for (int k0 = 0; k0 < 128; k0 += 16) {
        __syncthreads();
        for (int i = tid; i < 16 * D3; i += 256)
            Bs[i] = B[(k0 + i / D3) * D3 + (i % D3)];
        __syncthreads();
#pragma unroll
        for (int kk = 0; kk < 16; kk++) {
            float a[4];
#pragma unroll
            for (int r = 0; r < 4; r++) a[r] = As[(k0 + kk) * 33 + rg4 + r];
#pragma unroll
            for (int s = 0; s < 3; s++) {
                float4 b = *(const float4*)&Bs[kk * D3 + s * 128 + cg4];
#pragma unroll
                for (int r = 0; r < 4; r++) {
                    acc[s][r][0] += a[r] * b.x;
                    acc[s][r][1] += a[r] * b.y;
                    acc[s][r][2] += a[r] * b.z;
                    acc[s][r][3] += a[r] * b.w;
                }
            }
        }
    }
#pragma unroll
    for (int s = 0; s < 3; s++)
#pragma unroll
        for (int r = 0; r < 4; r++)
#pragma unroll
            for (int c = 0; c < 4; c++)
                g_wxiou[(row0 + rg4 + r) * D3 + s * 128 + cg4 + c] =
                    acc[s][r][c] + bias[s * 128 + cg4 + c];
}

// ---------------------------------------------------------------------------
// K2: g_wxf = features[internal] @ W_f + b_f  (internal nodes only: 1023/tree)
// Logical rows 0..32735 map to global node t*2047 + (L % 1023), t = L / 1023.
// ---------------------------------------------------------------------------
__global__ __launch_bounds__(256) void k_gemm_wxf(
    const float* __restrict__ A, const float* __restrict__ B,
    const float* __restrict__ bias)
{
    __shared__ float As[128 * 33];
    __shared__ float Bs[16 * 128];
    const int tid = threadIdx.x;
    const int L0 = blockIdx.x * 32;

    for (int i = tid; i < 32 * 128; i += 256) {
        int r = i >> 7, k = i & 127;
        int L = L0 + r;
        int t = L / 1023;
        int rr = L - t * 1023;
        As[k * 33 + r] = A[(t * MTREE + rr) * 128 + k];
    }

    float acc[4][4];
#pragma unroll
    for (int r = 0; r < 4; r++)
#pragma unroll
        for (int c = 0; c < 4; c++) acc[r][c] = 0.0f;

    const int cg4 = (tid & 31) * 4;
    const int rg4 = (tid >> 5) * 4;

    for (int k0 = 0; k0 < 128; k0 += 16) {
        __syncthreads();
        for (int i = tid; i < 16 * 128; i += 256)
            Bs[i] = B[(k0 + (i >> 7)) * 128 + (i & 127)];
        __syncthreads();
#pragma unroll
        for (int kk = 0; kk < 16; kk++) {
            float a[4];
#pragma unroll
            for (int r = 0; r < 4; r++) a[r] = As[(k0 + kk) * 33 + rg4 + r];
            float4 b = *(const float4*)&Bs[kk * 128 + cg4];
#pragma unroll
            for (int r = 0; r < 4; r++) {
                acc[r][0] += a[r] * b.x;
                acc[r][1] += a[r] * b.y;
                acc[r][2] += a[r] * b.z;
                acc[r][3] += a[r] * b.w;
            }
        }
    }
#pragma unroll
    for (int r = 0; r < 4; r++) {
        int L = L0 + rg4 + r;
        int t = L / 1023;
        int rr = L - t * 1023;
        int g = t * MTREE + rr;
#pragma unroll
        for (int c = 0; c < 4; c++)
            g_wxf[g * 128 + cg4 + c] = acc[r][c] + bias[cg4 + c];
    }
}

// ---------------------------------------------------------------------------
// Leaf pass: nodes at depth 10 (in-tree idx 1023..2046). h_sum = c_sum = 0.
// ---------------------------------------------------------------------------
__global__ void k_leaf(float* __restrict__ h)
{
    int idx = blockIdx.x * 256 + threadIdx.x;   // 32768*128 total
    int lr = idx >> 7, c = idx & 127;
    int t = lr >> 10, r = lr & 1023;
    int g = t * MTREE + 1023 + r;
    float iv = sigf(g_wxiou[g * D3 + c]);
    float ov = sigf(g_wxiou[g * D3 + 128 + c]);
    float uv = tanhfast(g_wxiou[g * D3 + 256 + c]);
    float cn = iv * uv;
    g_c[g * 128 + c] = cn;
    h[g * 128 + c] = ov * tanhfast(cn);
}

// ---------------------------------------------------------------------------
// L1 (per level): forget gates for all children at depth dd+1:
//   g_f[child] = sigmoid(g_wxf[parent] + h[child] @ U_f)
// cs = log2(children per tree). Children start at CH-1, parents at CH/2-1.
// ---------------------------------------------------------------------------
__global__ __launch_bounds__(256) void k_level_f(
    const float* __restrict__ h, const float* __restrict__ Uf, int cs)
{
    __shared__ float As[128 * 33];
    __shared__ float Bs[16 * 128];
    const int tid = threadIdx.x;
    const int L0 = blockIdx.x * 32;
    const int CH = 1 << cs;
    const int Sc = CH - 1;
    const int Sp = (CH >> 1) - 1;

    for (int i = tid; i < 32 * 128; i += 256) {
        int r = i >> 7, k = i & 127;
        int L = L0 + r;
        int t = L >> cs;
        int rr = L & (CH - 1);
        As[k * 33 + r] = h[(t * MTREE + Sc + rr) * 128 + k];
    }

    float acc[4][4];
#pragma unroll
    for (int r = 0; r < 4; r++)
#pragma unroll
        for (int c = 0; c < 4; c++) acc[r][c] = 0.0f;

    const int cg4 = (tid & 31) * 4;
    const int rg4 = (tid >> 5) * 4;

    for (int k0 = 0; k0 < 128; k0 += 16) {
        __syncthreads();
        for (int i = tid; i < 16 * 128; i += 256)
            Bs[i] = Uf[(k0 + (i >> 7)) * 128 + (i & 127)];
        __syncthreads();
#pragma unroll
        for (int kk = 0; kk < 16; kk++) {
            float a[4];
#pragma unroll
            for (int r = 0; r < 4; r++) a[r] = As[(k0 + kk) * 33 + rg4 + r];
            float4 b = *(const float4*)&Bs[kk * 128 + cg4];
#pragma unroll
            for (int r = 0; r < 4; r++) {
                acc[r][0] += a[r] * b.x;
                acc[r][1] += a[r] * b.y;
                acc[r][2] += a[r] * b.z;
                acc[r][3] += a[r] * b.w;
            }
        }
    }
#pragma unroll
    for (int r = 0; r < 4; r++) {
        int L = L0 + rg4 + r;
        int t = L >> cs;
        int rr = L & (CH - 1);
        int gc = t * MTREE + Sc + rr;
        int gp = t * MTREE + Sp + (rr >> 1);
#pragma unroll
        for (int c = 0; c < 4; c++) {
            int col = cg4 + c;
            g_f[gc * 128 + col] = sigf(acc[r][c] + g_wxf[gp * 128 + col]);
        }
    }
}

// ---------------------------------------------------------------------------
// L2 (per level): for parents at depth dd:
//   iou = wx_iou[p] + (h[c1]+h[c2]) @ U_iou ;  i,o,u = sig,sig,tanh
//   c[p] = i*u + f[c1]*c[c1] + f[c2]*c[c2] ;  h[p] = o*tanh(c[p])
// ps = log2(parents per tree).
// ---------------------------------------------------------------------------
__global__ __launch_bounds__(256) void k_level_iou(
    float* __restrict__ h, const float* __restrict__ Uiou, int ps)
{
    __shared__ float As[128 * 33];
    __shared__ float Bs[16 * D3];
    const int tid = threadIdx.x;
    const int L0 = blockIdx.x * 32;
    const int P = 1 << ps;
    const int Sp = P - 1;
    const int Sc = 2 * P - 1;

    for (int i = tid; i < 32 * 128; i += 256) {
        int r = i >> 7, k = i & 127;
        int L = L0 + r;
        int t = L >> ps;
        int rr = L & (P - 1);
        int gc1 = t * MTREE + Sc + 2 * rr;
        As[k * 33 + r] = h[gc1 * 128 + k] + h[(gc1 + 1) * 128 + k];
    }

    float acc[3][4][4];
#pragma unroll
    for (int s = 0; s < 3; s++)
#pragma unroll
        for (int r = 0; r < 4; r++)
#pragma unroll
            for (int c = 0; c < 4; c++) acc[s][r][c] = 0.0f;

    const int cg4 = (tid & 31) * 4;
    const int rg4 = (tid >> 5) * 4;

    for (int k0 = 0; k0 < 128; k0 += 16) {
        __syncthreads();
        for (int i = tid; i < 16 * D3; i += 256)
            Bs[i] = Uiou[(k0 + i / D3) * D3 + (i % D3)];
        __syncthreads();
#pragma unroll
        for (int kk = 0; kk < 16; kk++) {
            float a[4];
#pragma unroll
            for (int r = 0; r < 4; r++) a[r] = As[(k0 + kk) * 33 + rg4 + r];
#pragma unroll
            for (int s = 0; s < 3; s++) {
                float4 b = *(const float4*)&Bs[kk * D3 + s * 128 + cg4];
#pragma unroll
                for (int r = 0; r < 4; r++) {
                    acc[s][r][0] += a[r] * b.x;
                    acc[s][r][1] += a[r] * b.y;
                    acc[s][r][2] += a[r] * b.z;
                    acc[s][r][3] += a[r] * b.w;
                }
            }
        }
    }
#pragma unroll
    for (int r = 0; r < 4; r++) {
        int L = L0 + rg4 + r;
        int t = L >> ps;
        int rr = L & (P - 1);
        int gp = t * MTREE + Sp + rr;
        int gc1 = t * MTREE + Sc + 2 * rr;
        int gc2 = gc1 + 1;
#pragma unroll
        for (int c = 0; c < 4; c++) {
            int col = cg4 + c;
            float iv = sigf(acc[0][r][c] + g_wxiou[gp * D3 + col]);
            float ov = sigf(acc[1][r][c] + g_wxiou[gp * D3 + 128 + col]);
            float uv = tanhfast(acc[2][r][c] + g_wxiou[gp * D3 + 256 + col]);
            float cn = iv * uv
                     + g_f[gc1 * 128 + col] * g_c[gc1 * 128 + col]
                     + g_f[gc2 * 128 + col] * g_c[gc2 * 128 + col];
            g_c[gp * 128 + col] = cn;
            h[gp * 128 + col] = ov * tanhfast(cn);
        }
    }
}

// ---------------------------------------------------------------------------
extern "C" void kernel_launch(void* const* d_in, const int* in_sizes, int n_in,
                              void* d_out, int out_size)
{
    const float* features = (const float*)d_in[0];
    const float* W_iou    = (const float*)d_in[1];
    const float* b_iou    = (const float*)d_in[2];
    const float* U_iou    = (const float*)d_in[3];
    const float* W_f      = (const float*)d_in[4];
    const float* b_f      = (const float*)d_in[5];
    const float* U_f      = (const float*)d_in[6];
    float* h = (float*)d_out;   // N x 128 fp32 output (hidden states)

    // Level-independent precompute
    k_gemm_wxiou<<<NN / 32, 256>>>(features, W_iou, b_iou);   // 2047 blocks
    k_gemm_wxf<<<(NT * 1023) / 32, 256>>>(features, W_f, b_f); // 1023 blocks

    // Leaves (depth 10): 32768 nodes
    k_leaf<<<(32768 * 128) / 256, 256>>>(h);

    // Bottom-up levels: parents at depth dd = 9 .. 0
    for (int dd = 9; dd >= 0; dd--) {
        int cs = dd + 1;                       // log2(children per tree)
        int blocksF = (NT << cs) / 32;         // 2P rows total
        k_level_f<<<blocksF, 256>>>(h, U_f, cs);
        int blocksP = (NT << dd) / 32;         // P rows total (>=1)
        if (blocksP < 1) blocksP = 1;
        k_level_iou<<<blocksP, 256>>>(h, U_iou, dd);
    }
}

// round 2
// speedup vs baseline: 1.3501x; 1.3501x over previous
#include <cuda_runtime.h>

#define D3 384
#define MT 2047          // nodes per tree
#define NN 65504         // 32 trees * 2047

// Scratch (device globals: no allocation in kernel_launch)
__device__ float g_wxiou[NN * D3];   // W_iou*x + b_iou (internal nodes only used)
__device__ float g_wxf[NN * 128];    // W_f*x + b_f (internal nodes)
__device__ float g_c[NN * 128];      // cell state
__device__ float g_f[NN * 128];      // forget gate keyed by CHILD node (levels dd>=5)

__device__ __forceinline__ float sigf(float x) {
    return 1.0f / (1.0f + __expf(-x));
}
__device__ __forceinline__ float tanhfast(float x) {
    return 1.0f - 2.0f / (__expf(2.0f * x) + 1.0f);
}

// ---------------------------------------------------------------------------
// K1: wxiou = features @ W_iou + b_iou  (65504 x 128 @ 128 x 384)
// BM=32, 256 threads, 4 rows x 4 cols x 3 sets. Leaf rows (rr>=1023) fused:
// write c,h directly instead of storing wxiou.
// ---------------------------------------------------------------------------
__global__ __launch_bounds__(256) void k_gemm_wxiou(
    const float* __restrict__ A, const float* __restrict__ B,
    const float* __restrict__ bias, float* __restrict__ h)
{
    __shared__ __align__(16) float As[128 * 36];   // As[k*36 + r]
    __shared__ __align__(16) float Bs[32 * D3];
    const int tid = threadIdx.x;
    const int row0 = blockIdx.x * 32;

    for (int i = tid; i < 32 * 128; i += 256) {
        int r = i >> 7, k = i & 127;
        As[k * 36 + r] = A[(row0 + r) * 128 + k];
    }

    float acc[3][4][4];
#pragma unroll
    for (int s = 0; s < 3; s++)
#pragma unroll
        for (int r = 0; r < 4; r++)
#pragma unroll
            for (int c = 0; c < 4; c++) acc[s][r][c] = 0.0f;

    const int cg4 = (tid & 31) * 4;
    const int rg = (tid >> 5) * 4;

    for (int k0 = 0; k0 < 128; k0 += 32) {
        __syncthreads();
        const float* Bsrc = B + k0 * D3;
        for (int i = tid * 4; i < 32 * D3; i += 1024)
            *(float4*)&Bs[i] = *(const float4*)&Bsrc[i];
        __syncthreads();
#pragma unroll 8
        for (int kk = 0; kk < 32; kk++) {
            float4 a4 = *(const float4*)&As[(k0 + kk) * 36 + rg];
            float a[4] = {a4.x, a4.y, a4.z, a4.w};
#pragma unroll
            for (int s = 0; s < 3; s++) {
                float4 b = *(const float4*)&Bs[kk * D3 + s * 128 + cg4];
#pragma unroll
                for (int r = 0; r < 4; r++) {
                    acc[s][r][0] += a[r] * b.x;
                    acc[s][r][1] += a[r] * b.y;
                    acc[s][r][2] += a[r] * b.z;
                    acc[s][r][3] += a[r] * b.w;
                }
            }
        }
    }
#pragma unroll
    for (int r = 0; r < 4; r++) {
        int g = row0 + rg + r;
        int t = g / MT;
        int rr = g - t * MT;
        if (rr >= 1023) {   // leaf: finish LSTM cell now
#pragma unroll
            for (int c = 0; c < 4; c++) {
                int col = cg4 + c;
                float iv = sigf(acc[0][r][c] + bias[col]);
                float ov = sigf(acc[1][r][c] + bias[128 + col]);
                float uv = tanhfast(acc[2][r][c] + bias[256 + col]);
                float cn = iv * uv;
                g_c[g * 128 + col] = cn;
                h[g * 128 + col] = ov * tanhfast(cn);
            }
        } else {
#pragma unroll
            for (int s = 0; s < 3; s++)
#pragma unroll
                for (int c = 0; c < 4; c++)
                    g_wxiou[g * D3 + s * 128 + cg4 + c] =
                        acc[s][r][c] + bias[s * 128 + cg4 + c];
        }
    }
}

// ---------------------------------------------------------------------------
// K2: wxf = features[internal] @ W_f + b_f. 128 threads, BM=32, 8x4 tile.
// Logical rows L in [0, 32736): t = L/1023, node = t*2047 + L%1023.
// ---------------------------------------------------------------------------
__global__ __launch_bounds__(128) void k_gemm_wxf(
    const float* __restrict__ A, const float* __restrict__ B,
    const float* __restrict__ bias)
{
    __shared__ __align__(16) float As[128 * 36];
    __shared__ __align__(16) float Bs[32 * 128];
    const int tid = threadIdx.x;
    const int L0 = blockIdx.x * 32;

    for (int i = tid; i < 32 * 128; i += 128) {
        int r = i >> 7, k = i & 127;
        int L = L0 + r;
        int t = L / 1023;
        int rr = L - t * 1023;
        As[k * 36 + r] = A[(t * MT + rr) * 128 + k];
    }

    float acc[8][4];
#pragma unroll
    for (int r = 0; r < 8; r++)
#pragma unroll
        for (int c = 0; c < 4; c++) acc[r][c] = 0.0f;

    const int cg4 = (tid & 31) * 4;
    const int rg = (tid >> 5) * 8;

    for (int k0 = 0; k0 < 128; k0 += 32) {
        __syncthreads();
        const float* Bsrc = B + k0 * 128;
        for (int i = tid * 4; i < 32 * 128; i += 512)
            *(float4*)&Bs[i] = *(const float4*)&Bsrc[i];
        __syncthreads();
#pragma unroll 8
        for (int kk = 0; kk < 32; kk++) {
            float4 aL = *(const float4*)&As[(k0 + kk) * 36 + rg];
            float4 aH = *(const float4*)&As[(k0 + kk) * 36 + rg + 4];
            float a[8] = {aL.x, aL.y, aL.z, aL.w, aH.x, aH.y, aH.z, aH.w};
            float4 b = *(const float4*)&Bs[kk * 128 + cg4];
#pragma unroll
            for (int r = 0; r < 8; r++) {
                acc[r][0] += a[r] * b.x;
                acc[r][1] += a[r] * b.y;
                acc[r][2] += a[r] * b.z;
                acc[r][3] += a[r] * b.w;
            }
        }
    }
#pragma unroll
    for (int r = 0; r < 8; r++) {
        int L = L0 + rg + r;
        int t = L / 1023;
        int rr = L - t * 1023;
        int g = t * MT + rr;
#pragma unroll
        for (int c = 0; c < 4; c++)
            g_wxf[g * 128 + cg4 + c] = acc[r][c] + bias[cg4 + c];
    }
}

// ---------------------------------------------------------------------------
// K3 (levels dd>=5): forget gates for children at depth dd+1.
//   g_f[child] = sigmoid(wxf[parent] + h[child] @ U_f)
// 128 threads, BM=32 child rows, 8x4 tile. cs = dd+1.
// ---------------------------------------------------------------------------
__global__ __launch_bounds__(128) void k_level_f(
    const float* __restrict__ h, const float* __restrict__ Uf, int cs)
{
    __shared__ __align__(16) float As[128 * 36];
    __shared__ __align__(16) float Bs[32 * 128];
    const int tid = threadIdx.x;
    const int L0 = blockIdx.x * 32;
    const int CH = 1 << cs;
    const int Sc = CH - 1;
    const int Sp = (CH >> 1) - 1;

    for (int i = tid; i < 32 * 128; i += 128) {
        int r = i >> 7, k = i & 127;
        int L = L0 + r;
        int t = L >> cs;
        int rr = L & (CH - 1);
        As[k * 36 + r] = h[(t * MT + Sc + rr) * 128 + k];
    }

    float acc[8][4];
#pragma unroll
    for (int r = 0; r < 8; r++)
#pragma unroll
        for (int c = 0; c < 4; c++) acc[r][c] = 0.0f;

    const int cg4 = (tid & 31) * 4;
    const int rg = (tid >> 5) * 8;

    for (int k0 = 0; k0 < 128; k0 += 32) {
        __syncthreads();
        const float* Bsrc = Uf + k0 * 128;
        for (int i = tid * 4; i < 32 * 128; i += 512)
            *(float4*)&Bs[i] = *(const float4*)&Bsrc[i];
        __syncthreads();
#pragma unroll 8
        for (int kk = 0; kk < 32; kk++) {
            float4 aL = *(const float4*)&As[(k0 + kk) * 36 + rg];
            float4 aH = *(const float4*)&As[(k0 + kk) * 36 + rg + 4];
            float a[8] = {aL.x, aL.y, aL.z, aL.w, aH.x, aH.y, aH.z, aH.w};
            float4 b = *(const float4*)&Bs[kk * 128 + cg4];
#pragma unroll
            for (int r = 0; r < 8; r++) {
                acc[r][0] += a[r] * b.x;
                acc[r][1] += a[r] * b.y;
                acc[r][2] += a[r] * b.z;
                acc[r][3] += a[r] * b.w;
            }
        }
    }
#pragma unroll
    for (int r = 0; r < 8; r++) {
        int L = L0 + rg + r;
        int t = L >> cs;
        int rr = L & (CH - 1);
        int gc = t * MT + Sc + rr;
        int gp = t * MT + Sp + (rr >> 1);
#pragma unroll
        for (int c = 0; c < 4; c++) {
            int col = cg4 + c;
            g_f[gc * 128 + col] = sigf(acc[r][c] + g_wxf[gp * 128 + col]);
        }
    }
}

// ---------------------------------------------------------------------------
// K4 (levels dd>=5): parents at depth dd.
//   iou = wxiou[p] + (h[c1]+h[c2]) @ U_iou; c,h update using g_f,g_c.
// 256 threads, BM=32 parent rows, 4x4x3 tile. ps = dd.
// ---------------------------------------------------------------------------
__global__ __launch_bounds__(256) void k_level_iou(
    float* __restrict__ h, const float* __restrict__ Uiou, int ps)
{
    __shared__ __align__(16) float As[128 * 36];
    __shared__ __align__(16) float Bs[32 * D3];
    const int tid = threadIdx.x;
    const int L0 = blockIdx.x * 32;
    const int P = 1 << ps;
    const int Sp = P - 1;
    const int Sc = 2 * P - 1;

    for (int i = tid; i < 32 * 128; i += 256) {
        int r = i >> 7, k = i & 127;
        int L = L0 + r;
        int t = L >> ps;
        int rr = L & (P - 1);
        int gc1 = t * MT + Sc + 2 * rr;
        As[k * 36 + r] = h[gc1 * 128 + k] + h[(gc1 + 1) * 128 + k];
    }

    float acc[3][4][4];
#pragma unroll
    for (int s = 0; s < 3; s++)
#pragma unroll
        for (int r = 0; r < 4; r++)
#pragma unroll
            for (int c = 0; c < 4; c++) acc[s][r][c] = 0.0f;

    const int cg4 = (tid & 31) * 4;
    const int rg = (tid >> 5) * 4;

    for (int k0 = 0; k0 < 128; k0 += 32) {
        __syncthreads();
        const float* Bsrc = Uiou + k0 * D3;
        for (int i = tid * 4; i < 32 * D3; i += 1024)
            *(float4*)&Bs[i] = *(const float4*)&Bsrc[i];
        __syncthreads();
#pragma unroll 8
        for (int kk = 0; kk < 32; kk++) {
            float4 a4 = *(const float4*)&As[(k0 + kk) * 36 + rg];
            float a[4] = {a4.x, a4.y, a4.z, a4.w};
#pragma unroll
            for (int s = 0; s < 3; s++) {
                float4 b = *(const float4*)&Bs[kk * D3 + s * 128 + cg4];
#pragma unroll
                for (int r = 0; r < 4; r++) {
                    acc[s][r][0] += a[r] * b.x;
                    acc[s][r][1] += a[r] * b.y;
                    acc[s][r][2] += a[r] * b.z;
                    acc[s][r][3] += a[r] * b.w;
                }
            }
        }
    }
#pragma unroll
    for (int r = 0; r < 4; r++) {
        int L = L0 + rg + r;
        int t = L >> ps;
        int rr = L & (P - 1);
        int gp = t * MT + Sp + rr;
        int gc1 = t * MT + Sc + 2 * rr;
        int gc2 = gc1 + 1;
#pragma unroll
        for (int c = 0; c < 4; c++) {
            int col = cg4 + c;
            float iv = sigf(acc[0][r][c] + g_wxiou[gp * D3 + col]);
            float ov = sigf(acc[1][r][c] + g_wxiou[gp * D3 + 128 + col]);
            float uv = tanhfast(acc[2][r][c] + g_wxiou[gp * D3 + 256 + col]);
            float cn = iv * uv
                     + g_f[gc1 * 128 + col] * g_c[gc1 * 128 + col]
                     + g_f[gc2 * 128 + col] * g_c[gc2 * 128 + col];
            g_c[gp * 128 + col] = cn;
            h[gp * 128 + col] = ov * tanhfast(cn);
        }
    }
}

// ---------------------------------------------------------------------------
// K5: tail — levels dd=4..0 in ONE kernel, one block per tree.
// Per level: load child h into smem, compute F (2P x 128), stash f*c in smem,
// compute IOU (P x 384) + cell update. __syncthreads between phases.
// ---------------------------------------------------------------------------
__global__ __launch_bounds__(256) void k_tail(
    float* __restrict__ h, const float* __restrict__ Uf,
    const float* __restrict__ Uiou)
{
    __shared__ __align__(16) float Hs[32 * 128];
    __shared__ __align__(16) float FC[32 * 128];
    const int tid = threadIdx.x;
    const int base = blockIdx.x * MT;

    for (int dd = 4; dd >= 0; dd--) {
        const int P = 1 << dd;
        const int Sp = P - 1;
        const int Sc = 2 * P - 1;
        const int CR = 2 * P;

        __syncthreads();
        for (int i = tid; i < CR * 128; i += 256)
            Hs[i] = h[(base + Sc + (i >> 7)) * 128 + (i & 127)];
        __syncthreads();

        // F phase: for each child row r and col-quad
        for (int tt = tid; tt < CR * 32; tt += 256) {
            int r = tt >> 5;
            int col = (tt & 31) * 4;
            float4 acc = make_float4(0.f, 0.f, 0.f, 0.f);
#pragma unroll 4
            for (int k = 0; k < 128; k++) {
                float a = Hs[r * 128 + k];
                float4 b = *(const float4*)&Uf[k * 128 + col];
                acc.x += a * b.x; acc.y += a * b.y;
                acc.z += a * b.z; acc.w += a * b.w;
            }
            int gc = base + Sc + r;
            int gp = base + Sp + (r >> 1);
            float4 wf = *(const float4*)&g_wxf[gp * 128 + col];
            float4 cc = *(const float4*)&g_c[gc * 128 + col];
            float4 fc;
            fc.x = sigf(acc.x + wf.x) * cc.x;
            fc.y = sigf(acc.y + wf.y) * cc.y;
            fc.z = sigf(acc.z + wf.z) * cc.z;
            fc.w = sigf(acc.w + wf.w) * cc.w;
            *(float4*)&FC[r * 128 + col] = fc;
        }
        __syncthreads();

        // IOU phase: for each parent row r and col-quad (all 3 sets together)
        for (int tt = tid; tt < P * 32; tt += 256) {
            int r = tt >> 5;
            int col = (tt & 31) * 4;
            float4 a0 = make_float4(0.f, 0.f, 0.f, 0.f);
            float4 a1 = a0, a2 = a0;
#pragma unroll 4
            for (int k = 0; k < 128; k++) {
                float a = Hs[(2 * r) * 128 + k] + Hs[(2 * r + 1) * 128 + k];
                float4 b0 = *(const float4*)&Uiou[k * D3 + col];
                float4 b1 = *(const float4*)&Uiou[k * D3 + 128 + col];
                float4 b2 = *(const float4*)&Uiou[k * D3 + 256 + col];
                a0.x += a * b0.x; a0.y += a * b0.y; a0.z += a * b0.z; a0.w += a * b0.w;
                a1.x += a * b1.x; a1.y += a * b1.y; a1.z += a * b1.z; a1.w += a * b1.w;
                a2.x += a * b2.x; a2.y += a * b2.y; a2.z += a * b2.z; a2.w += a * b2.w;
            }
            int gp = base + Sp + r;
            float4 w0 = *(const float4*)&g_wxiou[gp * D3 + col];
            float4 w1 = *(const float4*)&g_wxiou[gp * D3 + 128 + col];
            float4 w2 = *(const float4*)&g_wxiou[gp * D3 + 256 + col];
            float4 f1 = *(const float4*)&FC[(2 * r) * 128 + col];
            float4 f2 = *(const float4*)&FC[(2 * r + 1) * 128 + col];
            float4 cres, hres;
            {
                float iv = sigf(a0.x + w0.x), ov = sigf(a1.x + w1.x);
                float uv = tanhfast(a2.x + w2.x);
                float cn = iv * uv + f1.x + f2.x;
                cres.x = cn; hres.x = ov * tanhfast(cn);
            }
            {
                float iv = sigf(a0.y + w0.y), ov = sigf(a1.y + w1.y);
                float uv = tanhfast(a2.y + w2.y);
                float cn = iv * uv + f1.y + f2.y;
                cres.y = cn; hres.y = ov * tanhfast(cn);
            }
            {
                float iv = sigf(a0.z + w0.z), ov = sigf(a1.z + w1.z);
                float uv = tanhfast(a2.z + w2.z);
                float cn = iv * uv + f1.z + f2.z;
                cres.z = cn; hres.z = ov * tanhfast(cn);
            }
            {
                float iv = sigf(a0.w + w0.w), ov = sigf(a1.w + w1.w);
                float uv = tanhfast(a2.w + w2.w);
                float cn = iv * uv + f1.w + f2.w;
                cres.w = cn; hres.w = ov * tanhfast(cn);
            }
            *(float4*)&g_c[gp * 128 + col] = cres;
            *(float4*)&h[gp * 128 + col] = hres;
        }
        __syncthreads();
    }
}

// ---------------------------------------------------------------------------
extern "C" void kernel_launch(void* const* d_in, const int* in_sizes, int n_in,
                              void* d_out, int out_size)
{
    const float* features = (const float*)d_in[0];
    const float* W_iou    = (const float*)d_in[1];
    const float* b_iou    = (const float*)d_in[2];
    const float* U_iou    = (const float*)d_in[3];
    const float* W_f      = (const float*)d_in[4];
    const float* b_f      = (const float*)d_in[5];
    const float* U_f      = (const float*)d_in[6];
    float* h = (float*)d_out;

    // Precompute (leaf cells fused into wxiou epilogue)
    k_gemm_wxiou<<<NN / 32, 256>>>(features, W_iou, b_iou, h);
    k_gemm_wxf<<<(32 * 1023) / 32, 128>>>(features, W_f, b_f);

    // Big levels: parents at depth dd = 9 .. 5
    for (int dd = 9; dd >= 5; dd--) {
        k_level_f<<<1 << (dd + 1), 128>>>(h, U_f, dd + 1);
        k_level_iou<<<1 << dd, 256>>>(h, U_iou, dd);
    }

    // Tail: levels 4..0, one block per tree
    k_tail<<<32, 256>>>(h, U_f, U_iou);
}

// round 3
// speedup vs baseline: 1.9201x; 1.4222x over previous
#include <cuda_runtime.h>
#include <cuda_bf16.h>
#include <cstdint>

#define D3 384
#define MT 2047          // nodes per tree
#define NT 32
#define NN 65504         // 32 * 2047
#define NINT 32736       // 32 * 1023 internal nodes

// ------------------------- device scratch ----------------------------------
__device__ float g_wxiou[NN * D3];      // W_iou*x + b_iou, all nodes
__device__ float g_wxf[NN * 128];       // W_f*x + b_f, internal nodes
__device__ float g_c[NN * 128];         // cell state
__device__ float g_fc[NN * 128];        // f(child)*c(child)
__device__ float g_uacc[16384 * 384];   // iou GEMM raw accumulator (per level)

__device__ __align__(16) __nv_bfloat16 g_Wiou_h[D3 * 128];
__device__ __align__(16) __nv_bfloat16 g_Wiou_l[D3 * 128];
__device__ __align__(16) __nv_bfloat16 g_Uiou_h[D3 * 128];
__device__ __align__(16) __nv_bfloat16 g_Uiou_l[D3 * 128];
__device__ __align__(16) __nv_bfloat16 g_Wf_h[128 * 128];
__device__ __align__(16) __nv_bfloat16 g_Wf_l[128 * 128];
__device__ __align__(16) __nv_bfloat16 g_Uf_h[128 * 128];
__device__ __align__(16) __nv_bfloat16 g_Uf_l[128 * 128];

__device__ __forceinline__ float sigf(float x) {
    return 1.0f / (1.0f + __expf(-x));
}
__device__ __forceinline__ float tanhfast(float x) {
    return 1.0f - 2.0f / (__expf(2.0f * x) + 1.0f);
}

// ------------------------- mma / ldmatrix helpers ---------------------------
__device__ __forceinline__ void ldsm4(uint32_t addr, uint32_t* r) {
    asm volatile("ldmatrix.sync.aligned.m8n8.x4.shared.b16 {%0,%1,%2,%3}, [%4];"
                 : "=r"(r[0]), "=r"(r[1]), "=r"(r[2]), "=r"(r[3]) : "r"(addr));
}
__device__ __forceinline__ void mma16816(float* c, const uint32_t* a,
                                         uint32_t b0, uint32_t b1) {
    asm volatile(
        "mma.sync.aligned.m16n8k16.row.col.f32.bf16.bf16.f32 "
        "{%0,%1,%2,%3}, {%4,%5,%6,%7}, {%8,%9}, {%0,%1,%2,%3};"
        : "+f"(c[0]), "+f"(c[1]), "+f"(c[2]), "+f"(c[3])
        : "r"(a[0]), "r"(a[1]), "r"(a[2]), "r"(a[3]), "r"(b0), "r"(b1));
}
__device__ __forceinline__ void split1(float v, __nv_bfloat16& h, __nv_bfloat16& l) {
    h = __float2bfloat16(v);
    l = __float2bfloat16(v - __bfloat162float(h));
}

// ------------------------- weight split kernel ------------------------------
__global__ void k_cvt(const float* __restrict__ Wiou, const float* __restrict__ Uiou,
                      const float* __restrict__ Wf, const float* __restrict__ Uf)
{
    int idx = blockIdx.x * 256 + threadIdx.x;     // 384*128
    int n = idx >> 7, k = idx & 127;
    split1(Wiou[k * D3 + n], g_Wiou_h[n * 128 + k], g_Wiou_l[n * 128 + k]);
    split1(Uiou[k * D3 + n], g_Uiou_h[n * 128 + k], g_Uiou_l[n * 128 + k]);
    if (n < 128) {
        split1(Wf[k * 128 + n], g_Wf_h[n * 128 + k], g_Wf_l[n * 128 + k]);
        split1(Uf[k * 128 + n], g_Uf_h[n * 128 + k], g_Uf_l[n * 128 + k]);
    }
}

// ------------------------- generic tensor-core GEMM -------------------------
// MODE 0: wxiou = features @ Wiou + b      (M=NN rows, N=384)
// MODE 1: wxf   = features[int] @ Wf + b   (M=NINT,    N=128)
// MODE 2: f-lvl: fc = sig(h_child@Uf + wxf[par]) * c_child  (N=128, lvl=cs)
// MODE 3: iou-lvl: uacc = (h_c1+h_c2)@Uiou (raw)            (N=384, lvl=ps)
#define SA 136   // smem row stride (bf16 elems): 272B = 17*16B -> ldmatrix conflict-free
#define SMEM_BYTES (4 * 64 * SA * 2)

template<int MODE>
__global__ __launch_bounds__(128) void k_mm(const float* __restrict__ Asrc,
                                            const float* __restrict__ bias,
                                            int lvl)
{
    extern __shared__ __nv_bfloat16 sm[];
    __nv_bfloat16* As_h = sm;
    __nv_bfloat16* As_l = sm + 64 * SA;
    __nv_bfloat16* Bs_h = sm + 2 * 64 * SA;
    __nv_bfloat16* Bs_l = sm + 3 * 64 * SA;

    const int tid = threadIdx.x;
    const int row0 = blockIdx.x * 64;
    const int nb = blockIdx.y;

    const __nv_bfloat16 *Bh, *Bl;
    if (MODE == 0)      { Bh = g_Wiou_h; Bl = g_Wiou_l; }
    else if (MODE == 1) { Bh = g_Wf_h;   Bl = g_Wf_l;   }
    else if (MODE == 2) { Bh = g_Uf_h;   Bl = g_Uf_l;   }
    else                { Bh = g_Uiou_h; Bl = g_Uiou_l; }

    // ---- load B tile (bf16, pre-split), rows nb*64..+63 ----
    {
        const int n0 = nb * 64;
#pragma unroll
        for (int s = 0; s < 8; s++) {
            int j = tid + s * 128;
            int r = j >> 4, q = j & 15;
            *(uint4*)&Bs_h[r * SA + q * 8] = *(const uint4*)&Bh[(n0 + r) * 128 + q * 8];
            *(uint4*)&Bs_l[r * SA + q * 8] = *(const uint4*)&Bl[(n0 + r) * 128 + q * 8];
        }
    }

    // ---- load A tile fp32, split into bf16 hi/lo ----
#pragma unroll
    for (int s = 0; s < 16; s++) {
        int j = tid + s * 128;
        int r = j >> 5, kq = j & 31;           // float4 column index
        int L = row0 + r;
        float4 v;
        if (MODE == 0) {
            int g = (L < NN) ? L : NN - 1;
            v = *(const float4*)&Asrc[g * 128 + kq * 4];
        } else if (MODE == 1) {
            int Lc = (L < NINT) ? L : NINT - 1;
            int t = Lc / 1023;
            int g = t * MT + (Lc - t * 1023);
            v = *(const float4*)&Asrc[g * 128 + kq * 4];
        } else if (MODE == 2) {
            int cs = lvl;
            int t = L >> cs, rr = L & ((1 << cs) - 1);
            int gc = t * MT + (1 << cs) - 1 + rr;
            v = *(const float4*)&Asrc[gc * 128 + kq * 4];
        } else {
            int ps = lvl;
            int t = L >> ps, rr = L & ((1 << ps) - 1);
            int gc1 = t * MT + (2 << ps) - 1 + 2 * rr;
            float4 v1 = *(const float4*)&Asrc[gc1 * 128 + kq * 4];
            float4 v2 = *(const float4*)&Asrc[(gc1 + 1) * 128 + kq * 4];
            v = make_float4(v1.x + v2.x, v1.y + v2.y, v1.z + v2.z, v1.w + v2.w);
        }
        __nv_bfloat16 h0, h1, h2, h3, l0, l1, l2, l3;
        split1(v.x, h0, l0); split1(v.y, h1, l1);
        split1(v.z, h2, l2); split1(v.w, h3, l3);
        __nv_bfloat162* dh = (__nv_bfloat162*)&As_h[r * SA + kq * 4];
        __nv_bfloat162* dl = (__nv_bfloat162*)&As_l[r * SA + kq * 4];
        __nv_bfloat162 p;
        p.x = h0; p.y = h1; dh[0] = p;
        p.x = h2; p.y = h3; dh[1] = p;
        p.x = l0; p.y = l1; dl[0] = p;
        p.x = l2; p.y = l3; dl[1] = p;
    }
    __syncthreads();

    // ---- warp tiling: 4 warps in 2x2, each 32m x 32n ----
    const int lane = tid & 31, wid = tid >> 5;
    const int wm = (wid & 1) * 32, wn = (wid >> 1) * 32;

    float acc[2][4][4];
#pragma unroll
    for (int i = 0; i < 2; i++)
#pragma unroll
        for (int j = 0; j < 4; j++)
#pragma unroll
            for (int k = 0; k < 4; k++) acc[i][j][k] = 0.0f;

    const uint32_t smbase = (uint32_t)__cvta_generic_to_shared(sm);
    const uint32_t offAl = 64 * SA * 2;
    const uint32_t offBh = 2 * 64 * SA * 2;
    const uint32_t offBl = 3 * 64 * SA * 2;

    const int rA = lane & 15;
    const int kA8 = (lane >> 4) * 8;
    uint32_t adA0 = smbase + ((wm + rA) * SA + kA8) * 2;
    uint32_t adA1 = smbase + ((wm + 16 + rA) * SA + kA8) * 2;
    const int rB = (lane & 7) + ((lane >> 4) * 8);
    const int kB8 = ((lane >> 3) & 1) * 8;
    uint32_t adB0 = smbase + offBh + ((wn + rB) * SA + kB8) * 2;
    uint32_t adB1 = smbase + offBh + ((wn + 16 + rB) * SA + kB8) * 2;

#pragma unroll
    for (int kc = 0; kc < 8; kc++) {
        const uint32_t ko = kc * 32;   // 16 bf16 = 32 bytes
        uint32_t a_h[2][4], a_l[2][4], b_h[2][4], b_l[2][4];
        ldsm4(adA0 + ko, a_h[0]);
        ldsm4(adA1 + ko, a_h[1]);
        ldsm4(adA0 + offAl + ko, a_l[0]);
        ldsm4(adA1 + offAl + ko, a_l[1]);
        ldsm4(adB0 + ko, b_h[0]);
        ldsm4(adB1 + ko, b_h[1]);
        ldsm4(adB0 + (offBl - offBh) + ko, b_l[0]);
        ldsm4(adB1 + (offBl - offBh) + ko, b_l[1]);
#pragma unroll
        for (int mi = 0; mi < 2; mi++)
#pragma unroll
            for (int nt = 0; nt < 4; nt++) {
                uint32_t bh0 = b_h[nt >> 1][(nt & 1) * 2];
                uint32_t bh1 = b_h[nt >> 1][(nt & 1) * 2 + 1];
                uint32_t bl0 = b_l[nt >> 1][(nt & 1) * 2];
                uint32_t bl1 = b_l[nt >> 1][(nt & 1) * 2 + 1];
                mma16816(acc[mi][nt], a_h[mi], bh0, bh1);
                mma16816(acc[mi][nt], a_l[mi], bh0, bh1);
                mma16816(acc[mi][nt], a_h[mi], bl0, bl1);
            }
    }

    // ---- epilogue ----
    const int er = lane >> 2;
    const int ec = (lane & 3) * 2;
#pragma unroll
    for (int mi = 0; mi < 2; mi++)
#pragma unroll
        for (int nt = 0; nt < 4; nt++) {
            int colL = wn + nt * 8 + ec;
            int n = nb * 64 + colL;
#pragma unroll
            for (int half = 0; half < 2; half++) {
                int lr = wm + mi * 16 + er + half * 8;
                int L = row0 + lr;
                float c0 = acc[mi][nt][half * 2 + 0];
                float c1 = acc[mi][nt][half * 2 + 1];
                if (MODE == 0) {
                    if (L < NN) {
                        float2 o;
                        o.x = c0 + bias[n];
                        o.y = c1 + bias[n + 1];
                        *(float2*)&g_wxiou[L * D3 + n] = o;
                    }
                } else if (MODE == 1) {
                    if (L < NINT) {
                        int t = L / 1023;
                        int g = t * MT + (L - t * 1023);
                        float2 o;
                        o.x = c0 + bias[n];
                        o.y = c1 + bias[n + 1];
                        *(float2*)&g_wxf[g * 128 + n] = o;
                    }
                } else if (MODE == 2) {
                    int cs = lvl;
                    int t = L >> cs, rr = L & ((1 << cs) - 1);
                    int gc = t * MT + (1 << cs) - 1 + rr;
                    int gp = t * MT + (1 << (cs - 1)) - 1 + (rr >> 1);
                    float2 wf = *(const float2*)&g_wxf[gp * 128 + n];
                    float2 cc = *(const float2*)&g_c[gc * 128 + n];
                    float2 o;
                    o.x = sigf(c0 + wf.x) * cc.x;
                    o.y = sigf(c1 + wf.y) * cc.y;
                    *(float2*)&g_fc[gc * 128 + n] = o;
                } else {
                    float2 o; o.x = c0; o.y = c1;
                    *(float2*)&g_uacc[L * D3 + n] = o;
                }
            }
        }
}

// ------------------------- elementwise kernels ------------------------------
__global__ void k_leaf(float* __restrict__ h)
{
    int idx = blockIdx.x * 256 + threadIdx.x;   // 32768*128
    int lr = idx >> 7, c = idx & 127;
    int t = lr >> 10, r = lr & 1023;
    int g = t * MT + 1023 + r;
    float iv = sigf(g_wxiou[g * D3 + c]);
    float ov = sigf(g_wxiou[g * D3 + 128 + c]);
    float uv = tanhfast(g_wxiou[g * D3 + 256 + c]);
    float cn = iv * uv;
    g_c[g * 128 + c] = cn;
    h[g * 128 + c] = ov * tanhfast(cn);
}

__global__ void k_combine(float* __restrict__ h, int ps)
{
    int idx = blockIdx.x * 256 + threadIdx.x;   // (NT<<ps)*128
    int p = idx >> 7, cc = idx & 127;
    int P = 1 << ps;
    int t = p >> ps, rr = p & (P - 1);
    int gp = t * MT + P - 1 + rr;
    int gc1 = t * MT + 2 * P - 1 + 2 * rr;
    float iv = sigf(g_uacc[p * D3 + cc]       + g_wxiou[gp * D3 + cc]);
    float ov = sigf(g_uacc[p * D3 + 128 + cc] + g_wxiou[gp * D3 + 128 + cc]);
    float uv = tanhfast(g_uacc[p * D3 + 256 + cc] + g_wxiou[gp * D3 + 256 + cc]);
    float cn = iv * uv + g_fc[gc1 * 128 + cc] + g_fc[(gc1 + 1) * 128 + cc];
    g_c[gp * 128 + cc] = cn;
    h[gp * 128 + cc] = ov * tanhfast(cn);
}

// ------------------------- tail (levels 4..0), SIMT -------------------------
__global__ __launch_bounds__(256) void k_tail(
    float* __restrict__ h, const float* __restrict__ Uf,
    const float* __restrict__ Uiou)
{
    __shared__ __align__(16) float Hs[32 * 128];
    __shared__ __align__(16) float FC[32 * 128];
    const int tid = threadIdx.x;
    const int base = blockIdx.x * MT;

    for (int dd = 4; dd >= 0; dd--) {
        const int P = 1 << dd;
        const int Sp = P - 1;
        const int Sc = 2 * P - 1;
        const int CR = 2 * P;

        __syncthreads();
        for (int i = tid; i < CR * 128; i += 256)
            Hs[i] = h[(base + Sc + (i >> 7)) * 128 + (i & 127)];
        __syncthreads();

        for (int tt = tid; tt < CR * 32; tt += 256) {
            int r = tt >> 5;
            int col = (tt & 31) * 4;
            float4 acc = make_float4(0.f, 0.f, 0.f, 0.f);
#pragma unroll 4
            for (int k = 0; k < 128; k++) {
                float a = Hs[r * 128 + k];
                float4 b = *(const float4*)&Uf[k * 128 + col];
                acc.x += a * b.x; acc.y += a * b.y;
                acc.z += a * b.z; acc.w += a * b.w;
            }
            int gc = base + Sc + r;
            int gp = base + Sp + (r >> 1);
            float4 wf = *(const float4*)&g_wxf[gp * 128 + col];
            float4 cc = *(const float4*)&g_c[gc * 128 + col];
            float4 fc;
            fc.x = sigf(acc.x + wf.x) * cc.x;
            fc.y = sigf(acc.y + wf.y) * cc.y;
            fc.z = sigf(acc.z + wf.z) * cc.z;
            fc.w = sigf(acc.w + wf.w) * cc.w;
            *(float4*)&FC[r * 128 + col] = fc;
        }
        __syncthreads();

        for (int tt = tid; tt < P * 32; tt += 256) {
            int r = tt >> 5;
            int col = (tt & 31) * 4;
            float4 a0 = make_float4(0.f, 0.f, 0.f, 0.f);
            float4 a1 = a0, a2 = a0;
#pragma unroll 4
            for (int k = 0; k < 128; k++) {
                float a = Hs[(2 * r) * 128 + k] + Hs[(2 * r + 1) * 128 + k];
                float4 b0 = *(const float4*)&Uiou[k * D3 + col];
                float4 b1 = *(const float4*)&Uiou[k * D3 + 128 + col];
                float4 b2 = *(const float4*)&Uiou[k * D3 + 256 + col];
                a0.x += a * b0.x; a0.y += a * b0.y; a0.z += a * b0.z; a0.w += a * b0.w;
                a1.x += a * b1.x; a1.y += a * b1.y; a1.z += a * b1.z; a1.w += a * b1.w;
                a2.x += a * b2.x; a2.y += a * b2.y; a2.z += a * b2.z; a2.w += a * b2.w;
            }
            int gp = base + Sp + r;
            float4 w0 = *(const float4*)&g_wxiou[gp * D3 + col];
            float4 w1 = *(const float4*)&g_wxiou[gp * D3 + 128 + col];
            float4 w2 = *(const float4*)&g_wxiou[gp * D3 + 256 + col];
            float4 f1 = *(const float4*)&FC[(2 * r) * 128 + col];
            float4 f2 = *(const float4*)&FC[(2 * r + 1) * 128 + col];
            float4 cres, hres;
            {
                float iv = sigf(a0.x + w0.x), ov = sigf(a1.x + w1.x);
                float uv = tanhfast(a2.x + w2.x);
                float cn = iv * uv + f1.x + f2.x;
                cres.x = cn; hres.x = ov * tanhfast(cn);
            }
            {
                float iv = sigf(a0.y + w0.y), ov = sigf(a1.y + w1.y);
                float uv = tanhfast(a2.y + w2.y);
                float cn = iv * uv + f1.y + f2.y;
                cres.y = cn; hres.y = ov * tanhfast(cn);
            }
            {
                float iv = sigf(a0.z + w0.z), ov = sigf(a1.z + w1.z);
                float uv = tanhfast(a2.z + w2.z);
                float cn = iv * uv + f1.z + f2.z;
                cres.z = cn; hres.z = ov * tanhfast(cn);
            }
            {
                float iv = sigf(a0.w + w0.w), ov = sigf(a1.w + w1.w);
                float uv = tanhfast(a2.w + w2.w);
                float cn = iv * uv + f1.w + f2.w;
                cres.w = cn; hres.w = ov * tanhfast(cn);
            }
            *(float4*)&g_c[gp * 128 + col] = cres;
            *(float4*)&h[gp * 128 + col] = hres;
        }
        __syncthreads();
    }
}

// ---------------------------------------------------------------------------
extern "C" void kernel_launch(void* const* d_in, const int* in_sizes, int n_in,
                              void* d_out, int out_size)
{
    const float* features = (const float*)d_in[0];
    const float* W_iou    = (const float*)d_in[1];
    const float* b_iou    = (const float*)d_in[2];
    const float* U_iou    = (const float*)d_in[3];
    const float* W_f      = (const float*)d_in[4];
    const float* b_f      = (const float*)d_in[5];
    const float* U_f      = (const float*)d_in[6];
    float* h = (float*)d_out;

    cudaFuncSetAttribute(k_mm<0>, cudaFuncAttributeMaxDynamicSharedMemorySize, SMEM_BYTES);
    cudaFuncSetAttribute(k_mm<1>, cudaFuncAttributeMaxDynamicSharedMemorySize, SMEM_BYTES);
    cudaFuncSetAttribute(k_mm<2>, cudaFuncAttributeMaxDynamicSharedMemorySize, SMEM_BYTES);
    cudaFuncSetAttribute(k_mm<3>, cudaFuncAttributeMaxDynamicSharedMemorySize, SMEM_BYTES);

    // Split weights to bf16 hi/lo, transposed
    k_cvt<<<192, 256>>>(W_iou, U_iou, W_f, U_f);

    // Level-independent GEMMs
    k_mm<0><<<dim3(1024, 6), 128, SMEM_BYTES>>>(features, b_iou, 0);
    k_mm<1><<<dim3(512, 2), 128, SMEM_BYTES>>>(features, b_f, 0);

    // Leaves
    k_leaf<<<16384, 256>>>(h);

    // Big levels: parents at depth dd = 9..5
    for (int dd = 9; dd >= 5; dd--) {
        int childBlocks = (NT << (dd + 1)) / 64;
        int parBlocks   = (NT << dd) / 64;
        k_mm<2><<<dim3(childBlocks, 2), 128, SMEM_BYTES>>>(h, nullptr, dd + 1);
        k_mm<3><<<dim3(parBlocks, 6), 128, SMEM_BYTES>>>(h, nullptr, dd);
        k_combine<<<((NT << dd) * 128) / 256, 256>>>(h, dd);
    }

    // Tail: levels 4..0
    k_tail<<<32, 256>>>(h, U_f, U_iou);
}